// round 2
// baseline (speedup 1.0000x reference)
#include <cuda_runtime.h>

// Problem constants (fixed for this problem instance)
#define TT 4
#define NN 50000
#define DD 32
#define EE 800000

// Scratch (allocation-free rule: __device__ globals)
__device__ int   g_counts[NN];
__device__ int   g_offsets[NN];
__device__ int   g_cursor[NN];
__device__ int   g_csr[EE];
__device__ float g_dinv[NN];
__device__ float g_xw2[NN * TT * DD];   // layout [n][t][d], pre-scaled by dinv[n]
__device__ int   g_is64;

// ---------------------------------------------------------------------------
// 0) Detect whether edge_index is int64 or int32 (JAX x64-off downcasts).
//    For int64 little-endian with values in [0, 50000), every odd 32-bit word
//    (high half) is zero. For int32 random data that is astronomically unlikely.
__global__ void detect_kernel(const int* __restrict__ ei32) {
    if (blockIdx.x == 0 && threadIdx.x == 0) {
        int all0 = 1;
        #pragma unroll 1
        for (int i = 1; i < 256; i += 2) all0 &= (ei32[i] == 0);
        g_is64 = all0;
    }
}

__device__ __forceinline__ int load_idx(const void* ei, int elem, int is64) {
    if (is64) return (int)((const long long*)ei)[elem];
    return ((const int*)ei)[elem];
}

// ---------------------------------------------------------------------------
// 1) zero counts
__global__ void zero_counts_kernel() {
    int i = blockIdx.x * blockDim.x + threadIdx.x;
    if (i < NN) g_counts[i] = 0;
}

// 2) in-degree histogram (int atomics, spread addresses)
__global__ void count_kernel(const void* __restrict__ ei) {
    int i = blockIdx.x * blockDim.x + threadIdx.x;
    if (i < EE) {
        int is64 = g_is64;
        int dst = load_idx(ei, EE + i, is64);
        atomicAdd(&g_counts[dst], 1);
    }
}

// 3) exclusive scan over counts (single block), also compute dinv = rsqrt(deg+1)
__global__ void scan_kernel() {
    __shared__ int sh[1024];
    __shared__ int carry;
    int tid = threadIdx.x;
    if (tid == 0) carry = 0;
    __syncthreads();
    for (int base = 0; base < NN; base += 1024) {
        int i = base + tid;
        int v = (i < NN) ? g_counts[i] : 0;
        sh[tid] = v;
        __syncthreads();
        // Hillis-Steele inclusive scan
        #pragma unroll
        for (int off = 1; off < 1024; off <<= 1) {
            int x = (tid >= off) ? sh[tid - off] : 0;
            __syncthreads();
            sh[tid] += x;
            __syncthreads();
        }
        int excl = carry + sh[tid] - v;
        if (i < NN) {
            g_offsets[i] = excl;
            g_cursor[i]  = excl;
            g_dinv[i]    = rsqrtf((float)v + 1.0f);
        }
        __syncthreads();
        if (tid == 0) carry += sh[1023];
        __syncthreads();
    }
}

// 4) scatter src indices into per-dst CSR lists
__global__ void fill_kernel(const void* __restrict__ ei) {
    int i = blockIdx.x * blockDim.x + threadIdx.x;
    if (i < EE) {
        int is64 = g_is64;
        int src = load_idx(ei, i, is64);
        int dst = load_idx(ei, EE + i, is64);
        int pos = atomicAdd(&g_cursor[dst], 1);
        g_csr[pos] = src;
    }
}

// ---------------------------------------------------------------------------
// 5) xw2[n][t][d] = (sum_k s[t][n][k] * W[k][d]) * dinv[n]
//    One warp per (t, n) row. W staged in shared; s row broadcast via shfl.
__global__ void gemm_kernel(const float* __restrict__ s, const float* __restrict__ W) {
    __shared__ float Wsh[DD * DD];
    int tid = threadIdx.x;
    for (int k = tid; k < DD * DD; k += blockDim.x) Wsh[k] = W[k];
    __syncthreads();

    int t    = blockIdx.y;
    int n    = blockIdx.x * 8 + (tid >> 5);
    int lane = tid & 31;
    if (n >= NN) return;   // grid divides evenly (50000 = 6250*8); never taken

    float sval = s[(t * NN + n) * DD + lane];
    float acc = 0.f;
    #pragma unroll
    for (int k = 0; k < DD; k++)
        acc = fmaf(__shfl_sync(0xffffffffu, sval, k), Wsh[k * DD + lane], acc);

    g_xw2[(n * TT + t) * DD + lane] = acc * g_dinv[n];
}

// ---------------------------------------------------------------------------
// 6) Aggregation (L2-bound hot loop) fused with temporal-mean, IF dynamics,
//    and z update. One warp per dst node. During accumulation each lane owns
//    (t = lane>>3, float4 q = lane&7) so one edge = one LDG.128 per warp
//    covering the full 512B [T][D] tile of the source node. Warp-local
//    shared-memory transpose, then lane = d for the time recursion.
__global__ void agg_kernel(const float* __restrict__ z,
                           float* __restrict__ o_out,
                           float* __restrict__ z_out) {
    __shared__ float4 sh4[8][TT * 8];   // [warp][t*8+q] : 4KB

    int wid  = threadIdx.x >> 5;
    int lane = threadIdx.x & 31;
    int n    = blockIdx.x * 8 + wid;
    if (n >= NN) return;               // grid divides evenly; never taken

    int t = lane >> 3;
    int q = lane & 7;

    const float4* base = (const float4*)g_xw2;
    // self-loop: x += xw[n]*dinv[n]^2 == dinv[n] * xw2[n]
    float4 acc = base[(n * TT + t) * 8 + q];

    int start = g_offsets[n];
    int deg   = g_counts[n];
    const int* __restrict__ csr = g_csr + start;

    int j = 0;
    for (; j + 4 <= deg; j += 4) {
        int s0 = csr[j], s1 = csr[j + 1], s2 = csr[j + 2], s3 = csr[j + 3];
        float4 v0 = base[(s0 * TT + t) * 8 + q];
        float4 v1 = base[(s1 * TT + t) * 8 + q];
        float4 v2 = base[(s2 * TT + t) * 8 + q];
        float4 v3 = base[(s3 * TT + t) * 8 + q];
        acc.x += (v0.x + v1.x) + (v2.x + v3.x);
        acc.y += (v0.y + v1.y) + (v2.y + v3.y);
        acc.z += (v0.z + v1.z) + (v2.z + v3.z);
        acc.w += (v0.w + v1.w) + (v2.w + v3.w);
    }
    for (; j < deg; j++) {
        int sj = csr[j];
        float4 v = base[(sj * TT + t) * 8 + q];
        acc.x += v.x; acc.y += v.y; acc.z += v.z; acc.w += v.w;
    }

    float dn = g_dinv[n];
    acc.x *= dn; acc.y *= dn; acc.z *= dn; acc.w *= dn;
    sh4[wid][t * 8 + q] = acc;
    __syncwarp();

    const float* shf = (const float*)&sh4[wid][0];   // [TT][DD] floats
    float v = 0.f, ysum = 0.f;
    #pragma unroll
    for (int ttt = 0; ttt < TT; ttt++) {
        float x = shf[ttt * DD + lane];
        ysum += x;
        v += x;
        float o = (v >= 1.0f) ? 1.0f : 0.0f;   // V_TH = 1
        v -= o;                                 // soft reset, o * V_TH
        o_out[(ttt * NN + n) * DD + lane] = o;
    }
    z_out[n * DD + lane] = z[n * DD + lane] + ysum * 0.25f;  // mean over T=4
}

// ---------------------------------------------------------------------------
extern "C" void kernel_launch(void* const* d_in, const int* in_sizes, int n_in,
                              void* d_out, int out_size) {
    const float* s  = (const float*)d_in[0];        // [T,N,D]
    const float* z  = (const float*)d_in[1];        // [N,D]
    const float* W  = (const float*)d_in[2];        // [D,D]
    const void*  ei = d_in[3];                      // [2,E] int64 or int32

    float* o_out = (float*)d_out;                   // [T,N,D]
    float* z_out = o_out + (size_t)TT * NN * DD;    // [N,D]

    detect_kernel<<<1, 32>>>((const int*)ei);
    zero_counts_kernel<<<(NN + 255) / 256, 256>>>();
    count_kernel<<<(EE + 255) / 256, 256>>>(ei);
    scan_kernel<<<1, 1024>>>();
    fill_kernel<<<(EE + 255) / 256, 256>>>(ei);
    dim3 gg((NN + 7) / 8, TT);
    gemm_kernel<<<gg, 256>>>(s, W);
    agg_kernel<<<(NN + 7) / 8, 256>>>(z, o_out, z_out);
}

// round 3
// speedup vs baseline: 1.6857x; 1.6857x over previous
#include <cuda_runtime.h>

// Problem constants (fixed for this problem instance)
#define TT 4
#define NN 50000
#define DD 32
#define EE 800000

// Scratch (allocation-free rule: __device__ globals)
__device__ int   g_counts[NN];
__device__ int   g_offsets[NN];
__device__ int   g_cursor[NN];
__device__ int   g_csr[EE];
__device__ float g_dinv[NN];
__device__ float g_xw2[NN * TT * DD];   // layout [n][t][d], pre-scaled by dinv[n]
__device__ int   g_is64;
__device__ int   g_total;               // bump allocator for CSR segments

// ---------------------------------------------------------------------------
// 0) Detect whether edge_index is int64 or int32 (JAX x64-off downcasts).
//    For int64 little-endian with values in [0, 50000), every odd 32-bit word
//    (high half) is zero. For int32 random data that is astronomically
//    unlikely (checked across 32 lanes in one shot).
__global__ void detect_kernel(const int* __restrict__ ei32) {
    int lane = threadIdx.x & 31;
    int v = ei32[1 + 2 * lane];          // odd words = high halves if int64
    unsigned nz = __ballot_sync(0xffffffffu, v != 0);
    if (lane == 0) g_is64 = (nz == 0u);
}

__device__ __forceinline__ int load_idx(const void* ei, int elem, int is64) {
    if (is64) return (int)((const long long*)ei)[elem];
    return ((const int*)ei)[elem];
}

// ---------------------------------------------------------------------------
// 1) zero counts + bump allocator
__global__ void zero_counts_kernel() {
    int i = blockIdx.x * blockDim.x + threadIdx.x;
    if (i < NN) g_counts[i] = 0;
    if (i == 0) g_total = 0;
}

// 2) in-degree histogram (int atomics, spread addresses)
__global__ void count_kernel(const void* __restrict__ ei) {
    int i = blockIdx.x * blockDim.x + threadIdx.x;
    if (i < EE) {
        int is64 = g_is64;
        int dst = load_idx(ei, EE + i, is64);
        atomicAdd(&g_counts[dst], 1);
    }
}

// 3) Segment assignment WITHOUT a global scan. CSR segments only need to be
//    disjoint, not ordered by node id: warp-inclusive scan of counts + one
//    atomicAdd per warp on a bump allocator. Full-chip, sync-free.
//    Also computes dinv = rsqrt(deg+1).
__global__ void offsets_kernel() {
    int i    = blockIdx.x * blockDim.x + threadIdx.x;
    int lane = threadIdx.x & 31;
    int v    = (i < NN) ? g_counts[i] : 0;

    // warp inclusive scan
    int incl = v;
    #pragma unroll
    for (int off = 1; off < 32; off <<= 1) {
        int x = __shfl_up_sync(0xffffffffu, incl, off);
        if (lane >= off) incl += x;
    }
    int wtotal = __shfl_sync(0xffffffffu, incl, 31);
    int base = 0;
    if (lane == 31) base = atomicAdd(&g_total, wtotal);
    base = __shfl_sync(0xffffffffu, base, 31);

    if (i < NN) {
        int excl = base + incl - v;
        g_offsets[i] = excl;
        g_cursor[i]  = excl;
        g_dinv[i]    = rsqrtf((float)v + 1.0f);
    }
}

// 4) scatter src indices into per-dst CSR lists
__global__ void fill_kernel(const void* __restrict__ ei) {
    int i = blockIdx.x * blockDim.x + threadIdx.x;
    if (i < EE) {
        int is64 = g_is64;
        int src = load_idx(ei, i, is64);
        int dst = load_idx(ei, EE + i, is64);
        int pos = atomicAdd(&g_cursor[dst], 1);
        g_csr[pos] = src;
    }
}

// ---------------------------------------------------------------------------
// 5) xw2[n][t][d] = (sum_k s[t][n][k] * W[k][d]) * dinv[n]
//    One warp per (t, n) row. W staged in shared; s row broadcast via shfl.
__global__ void gemm_kernel(const float* __restrict__ s, const float* __restrict__ W) {
    __shared__ float Wsh[DD * DD];
    int tid = threadIdx.x;
    for (int k = tid; k < DD * DD; k += blockDim.x) Wsh[k] = W[k];
    __syncthreads();

    int t    = blockIdx.y;
    int n    = blockIdx.x * 8 + (tid >> 5);
    int lane = tid & 31;
    if (n >= NN) return;   // grid divides evenly (50000 = 6250*8); never taken

    float sval = s[(t * NN + n) * DD + lane];
    float acc = 0.f;
    #pragma unroll
    for (int k = 0; k < DD; k++)
        acc = fmaf(__shfl_sync(0xffffffffu, sval, k), Wsh[k * DD + lane], acc);

    g_xw2[(n * TT + t) * DD + lane] = acc * g_dinv[n];
}

// ---------------------------------------------------------------------------
// 6) Aggregation (L2-bound hot loop) fused with temporal-mean, IF dynamics,
//    and z update. One warp per dst node. During accumulation each lane owns
//    (t = lane>>3, float4 q = lane&7) so one edge = one LDG.128 per warp
//    covering the full 512B [T][D] tile of the source node. Warp-local
//    shared-memory transpose, then lane = d for the time recursion.
__global__ void agg_kernel(const float* __restrict__ z,
                           float* __restrict__ o_out,
                           float* __restrict__ z_out) {
    __shared__ float4 sh4[8][TT * 8];   // [warp][t*8+q] : 4KB

    int wid  = threadIdx.x >> 5;
    int lane = threadIdx.x & 31;
    int n    = blockIdx.x * 8 + wid;
    if (n >= NN) return;               // grid divides evenly; never taken

    int t = lane >> 3;
    int q = lane & 7;

    const float4* base = (const float4*)g_xw2;
    // self-loop: x += xw[n]*dinv[n]^2 == dinv[n] * xw2[n]
    float4 acc = base[(n * TT + t) * 8 + q];

    int start = g_offsets[n];
    int deg   = g_counts[n];
    const int* __restrict__ csr = g_csr + start;

    int j = 0;
    for (; j + 4 <= deg; j += 4) {
        int s0 = csr[j], s1 = csr[j + 1], s2 = csr[j + 2], s3 = csr[j + 3];
        float4 v0 = base[(s0 * TT + t) * 8 + q];
        float4 v1 = base[(s1 * TT + t) * 8 + q];
        float4 v2 = base[(s2 * TT + t) * 8 + q];
        float4 v3 = base[(s3 * TT + t) * 8 + q];
        acc.x += (v0.x + v1.x) + (v2.x + v3.x);
        acc.y += (v0.y + v1.y) + (v2.y + v3.y);
        acc.z += (v0.z + v1.z) + (v2.z + v3.z);
        acc.w += (v0.w + v1.w) + (v2.w + v3.w);
    }
    for (; j < deg; j++) {
        int sj = csr[j];
        float4 v = base[(sj * TT + t) * 8 + q];
        acc.x += v.x; acc.y += v.y; acc.z += v.z; acc.w += v.w;
    }

    float dn = g_dinv[n];
    acc.x *= dn; acc.y *= dn; acc.z *= dn; acc.w *= dn;
    sh4[wid][t * 8 + q] = acc;
    __syncwarp();

    const float* shf = (const float*)&sh4[wid][0];   // [TT][DD] floats
    float v = 0.f, ysum = 0.f;
    #pragma unroll
    for (int ttt = 0; ttt < TT; ttt++) {
        float x = shf[ttt * DD + lane];
        ysum += x;
        v += x;
        float o = (v >= 1.0f) ? 1.0f : 0.0f;   // V_TH = 1
        v -= o;                                 // soft reset, o * V_TH
        o_out[(ttt * NN + n) * DD + lane] = o;
    }
    z_out[n * DD + lane] = z[n * DD + lane] + ysum * 0.25f;  // mean over T=4
}

// ---------------------------------------------------------------------------
extern "C" void kernel_launch(void* const* d_in, const int* in_sizes, int n_in,
                              void* d_out, int out_size) {
    const float* s  = (const float*)d_in[0];        // [T,N,D]
    const float* z  = (const float*)d_in[1];        // [N,D]
    const float* W  = (const float*)d_in[2];        // [D,D]
    const void*  ei = d_in[3];                      // [2,E] int64 or int32

    float* o_out = (float*)d_out;                   // [T,N,D]
    float* z_out = o_out + (size_t)TT * NN * DD;    // [N,D]

    detect_kernel<<<1, 32>>>((const int*)ei);
    zero_counts_kernel<<<(NN + 255) / 256, 256>>>();
    count_kernel<<<(EE + 255) / 256, 256>>>(ei);
    offsets_kernel<<<(NN + 255) / 256, 256>>>();
    fill_kernel<<<(EE + 255) / 256, 256>>>(ei);
    dim3 gg((NN + 7) / 8, TT);
    gemm_kernel<<<gg, 256>>>(s, W);
    agg_kernel<<<(NN + 7) / 8, 256>>>(z, o_out, z_out);
}

// round 4
// speedup vs baseline: 1.7157x; 1.0178x over previous
#include <cuda_runtime.h>

// Problem constants (fixed for this problem instance)
#define TT 4
#define NN 50000
#define DD 32
#define EE 800000

// Scratch (allocation-free rule: __device__ globals)
__device__ int   g_counts[NN];
__device__ int   g_offsets[NN];
__device__ int   g_cursor[NN];
__device__ int   g_csr[EE];
__device__ float g_dinv[NN];
__device__ float g_xw2[NN * TT * DD];   // layout [n][t][d], pre-scaled by dinv[n]
__device__ int   g_is64;
__device__ int   g_total;               // bump allocator for CSR segments

__device__ __forceinline__ int load_idx(const void* ei, int elem, int is64) {
    if (is64) return (int)((const long long*)ei)[elem];
    return ((const int*)ei)[elem];
}

// ---------------------------------------------------------------------------
// 1) zero counts + bump allocator, and detect int64-vs-int32 edge_index
//    (JAX x64-off downcasts). For int64 little-endian with values < 50000,
//    every odd 32-bit word (high half) is zero; checked across 32 lanes.
__global__ void init_kernel(const int* __restrict__ ei32) {
    int i = blockIdx.x * blockDim.x + threadIdx.x;
    if (i < NN) g_counts[i] = 0;
    if (blockIdx.x == 0 && threadIdx.x < 32) {
        int v = ei32[1 + 2 * threadIdx.x];
        unsigned nz = __ballot_sync(0xffffffffu, v != 0);
        if (threadIdx.x == 0) { g_is64 = (nz == 0u); g_total = 0; }
    }
}

// 2) in-degree histogram (int atomics, spread addresses)
__global__ void count_kernel(const void* __restrict__ ei) {
    int i = blockIdx.x * blockDim.x + threadIdx.x;
    if (i < EE) {
        int is64 = g_is64;
        int dst = load_idx(ei, EE + i, is64);
        atomicAdd(&g_counts[dst], 1);
    }
}

// 3) Segment assignment WITHOUT a global scan. CSR segments only need to be
//    disjoint, not ordered by node id: warp-inclusive scan of counts + one
//    atomicAdd per warp on a bump allocator. Full-chip, sync-free.
//    Also computes dinv = rsqrt(deg+1).
__global__ void offsets_kernel() {
    int i    = blockIdx.x * blockDim.x + threadIdx.x;
    int lane = threadIdx.x & 31;
    int v    = (i < NN) ? g_counts[i] : 0;

    // warp inclusive scan
    int incl = v;
    #pragma unroll
    for (int off = 1; off < 32; off <<= 1) {
        int x = __shfl_up_sync(0xffffffffu, incl, off);
        if (lane >= off) incl += x;
    }
    int wtotal = __shfl_sync(0xffffffffu, incl, 31);
    int base = 0;
    if (lane == 31) base = atomicAdd(&g_total, wtotal);
    base = __shfl_sync(0xffffffffu, base, 31);

    if (i < NN) {
        int excl = base + incl - v;
        g_offsets[i] = excl;
        g_cursor[i]  = excl;
        g_dinv[i]    = rsqrtf((float)v + 1.0f);
    }
}

// 4) scatter src indices into per-dst CSR lists
__global__ void fill_kernel(const void* __restrict__ ei) {
    int i = blockIdx.x * blockDim.x + threadIdx.x;
    if (i < EE) {
        int is64 = g_is64;
        int src = load_idx(ei, i, is64);
        int dst = load_idx(ei, EE + i, is64);
        int pos = atomicAdd(&g_cursor[dst], 1);
        g_csr[pos] = src;
    }
}

// ---------------------------------------------------------------------------
// 5) xw2[n][t][d] = (sum_k s[t][n][k] * W[k][d]) * dinv[n]
//    One warp per (t, n) row. W staged in shared; s row broadcast via shfl.
//    Runs on a forked stream concurrently with fill_kernel (independent).
__global__ void gemm_kernel(const float* __restrict__ s, const float* __restrict__ W) {
    __shared__ float Wsh[DD * DD];
    int tid = threadIdx.x;
    for (int k = tid; k < DD * DD; k += blockDim.x) Wsh[k] = W[k];
    __syncthreads();

    int t    = blockIdx.y;
    int n    = blockIdx.x * 8 + (tid >> 5);
    int lane = tid & 31;

    float sval = s[(t * NN + n) * DD + lane];
    float acc = 0.f;
    #pragma unroll
    for (int k = 0; k < DD; k++)
        acc = fmaf(__shfl_sync(0xffffffffu, sval, k), Wsh[k * DD + lane], acc);

    g_xw2[(n * TT + t) * DD + lane] = acc * g_dinv[n];
}

// ---------------------------------------------------------------------------
// 6) Aggregation (L2-bound hot loop) fused with temporal-mean, IF dynamics,
//    and z update. One warp per dst node. During accumulation each lane owns
//    (t = lane>>3, float4 q = lane&7) so one edge = one LDG.128 per warp
//    covering the full 512B [T][D] tile of the source node. Warp-local
//    shared-memory transpose, then lane = d for the time recursion.
__global__ void agg_kernel(const float* __restrict__ z,
                           float* __restrict__ o_out,
                           float* __restrict__ z_out) {
    __shared__ float4 sh4[8][TT * 8];   // [warp][t*8+q] : 4KB

    int wid  = threadIdx.x >> 5;
    int lane = threadIdx.x & 31;
    int n    = blockIdx.x * 8 + wid;

    int t = lane >> 3;
    int q = lane & 7;

    const float4* base = (const float4*)g_xw2;
    // self-loop: x += xw[n]*dinv[n]^2 == dinv[n] * xw2[n]
    float4 acc = base[(n * TT + t) * 8 + q];

    int start = g_offsets[n];
    int deg   = g_counts[n];
    const int* __restrict__ csr = g_csr + start;

    int j = 0;
    for (; j + 4 <= deg; j += 4) {
        int s0 = csr[j], s1 = csr[j + 1], s2 = csr[j + 2], s3 = csr[j + 3];
        float4 v0 = base[(s0 * TT + t) * 8 + q];
        float4 v1 = base[(s1 * TT + t) * 8 + q];
        float4 v2 = base[(s2 * TT + t) * 8 + q];
        float4 v3 = base[(s3 * TT + t) * 8 + q];
        acc.x += (v0.x + v1.x) + (v2.x + v3.x);
        acc.y += (v0.y + v1.y) + (v2.y + v3.y);
        acc.z += (v0.z + v1.z) + (v2.z + v3.z);
        acc.w += (v0.w + v1.w) + (v2.w + v3.w);
    }
    for (; j < deg; j++) {
        int sj = csr[j];
        float4 v = base[(sj * TT + t) * 8 + q];
        acc.x += v.x; acc.y += v.y; acc.z += v.z; acc.w += v.w;
    }

    float dn = g_dinv[n];
    acc.x *= dn; acc.y *= dn; acc.z *= dn; acc.w *= dn;
    sh4[wid][t * 8 + q] = acc;
    __syncwarp();

    const float* shf = (const float*)&sh4[wid][0];   // [TT][DD] floats
    float v = 0.f, ysum = 0.f;
    #pragma unroll
    for (int ttt = 0; ttt < TT; ttt++) {
        float x = shf[ttt * DD + lane];
        ysum += x;
        v += x;
        float o = (v >= 1.0f) ? 1.0f : 0.0f;   // V_TH = 1
        v -= o;                                 // soft reset, o * V_TH
        o_out[(ttt * NN + n) * DD + lane] = o;
    }
    z_out[n * DD + lane] = z[n * DD + lane] + ysum * 0.25f;  // mean over T=4
}

// ---------------------------------------------------------------------------
extern "C" void kernel_launch(void* const* d_in, const int* in_sizes, int n_in,
                              void* d_out, int out_size) {
    const float* s  = (const float*)d_in[0];        // [T,N,D]
    const float* z  = (const float*)d_in[1];        // [N,D]
    const float* W  = (const float*)d_in[2];        // [D,D]
    const void*  ei = d_in[3];                      // [2,E] int64 or int32

    float* o_out = (float*)d_out;                   // [T,N,D]
    float* z_out = o_out + (size_t)TT * NN * DD;    // [N,D]

    // Lazily-created side stream + events (host objects, not device memory).
    // Created on the first (eager, pre-capture) call; reused thereafter so
    // nothing is created during graph capture.
    static cudaStream_t s2 = nullptr;
    static cudaEvent_t ev_fork = nullptr, ev_join = nullptr;
    if (s2 == nullptr) {
        cudaStreamCreateWithFlags(&s2, cudaStreamNonBlocking);
        cudaEventCreateWithFlags(&ev_fork, cudaEventDisableTiming);
        cudaEventCreateWithFlags(&ev_join, cudaEventDisableTiming);
    }

    init_kernel<<<(NN + 255) / 256, 256>>>((const int*)ei);
    count_kernel<<<(EE + 255) / 256, 256>>>(ei);
    offsets_kernel<<<(NN + 255) / 256, 256>>>();

    // Fork: fill (edge scatter) and gemm (dense transform) are independent.
    cudaEventRecord(ev_fork, 0);
    cudaStreamWaitEvent(s2, ev_fork, 0);

    fill_kernel<<<(EE + 255) / 256, 256>>>(ei);              // main stream

    dim3 gg((NN + 7) / 8, TT);
    gemm_kernel<<<gg, 256, 0, s2>>>(s, W);                   // side stream
    cudaEventRecord(ev_join, s2);

    cudaStreamWaitEvent(0, ev_join, 0);                      // join
    agg_kernel<<<(NN + 7) / 8, 256>>>(z, o_out, z_out);
}